// round 13
// baseline (speedup 1.0000x reference)
#include <cuda_runtime.h>
#include <math.h>
#include <stdint.h>

// NT-Xent loss. N=8192 rows (interleaved zjs/zis), D=256.
// score = 2*cos(i,j) in [-2,2] -> fixed-shift logsumexp:
//   loss_i = 2 + ln(sum_{j!=i} exp(2 d_ij - 2)) - 2 d_{i, i^1}
// Symmetric int8 IMMA GEMM. Persistent CTAs with a dynamic TICKET scheduler
// (1 atomicAdd per 128x128 tile, 1-tile lookahead) + cross-tile 3-stage
// cp.async ring: next tile's loads hide under current tile's compute.

#define NROWS 8192
#define DIM   256
#define NT_TOT 2080

__device__ __align__(16) int8_t g_q[NROWS * DIM];   // 2 MB quantized rows
__device__ __align__(16) float g_sc[NROWS];         // per-row dequant scale
__device__ float g_rowsum[NROWS];
__device__ float g_tdot[NROWS];
__device__ unsigned int g_ticket;

#define SMEM_TOTAL 98304   // 3 stages x 32 KB

// ---------------- helpers ----------------
__device__ __forceinline__ uint32_t smem_u32(const void* p) {
    uint32_t a;
    asm("{ .reg .u64 t; cvta.to.shared.u64 t, %1; cvt.u32.u64 %0, t; }"
        : "=r"(a) : "l"(p));
    return a;
}
__device__ __forceinline__ void cp16(uint32_t dst, const void* src) {
    asm volatile("cp.async.cg.shared.global [%0], [%1], 16;"
                 :: "r"(dst), "l"(src) : "memory");
}
__device__ __forceinline__ void ldsm_x4(uint32_t* r, uint32_t addr) {
    asm volatile("ldmatrix.sync.aligned.m8n8.x4.shared.b16 {%0,%1,%2,%3}, [%4];"
                 : "=r"(r[0]), "=r"(r[1]), "=r"(r[2]), "=r"(r[3]) : "r"(addr));
}
__device__ __forceinline__ void imma16832(int* c, const uint32_t* a,
                                          uint32_t b0, uint32_t b1) {
    asm volatile("mma.sync.aligned.m16n8k32.row.col.s32.s8.s8.s32 "
                 "{%0,%1,%2,%3}, {%4,%5,%6,%7}, {%8,%9}, {%0,%1,%2,%3};"
                 : "+r"(c[0]), "+r"(c[1]), "+r"(c[2]), "+r"(c[3])
                 : "r"(a[0]), "r"(a[1]), "r"(a[2]), "r"(a[3]), "r"(b0), "r"(b1));
}
__device__ __forceinline__ float fexp2(float x) {
    float e; asm("ex2.approx.ftz.f32 %0, %1;" : "=f"(e) : "f"(x)); return e;
}
__device__ __forceinline__ float flg2(float x) {
    float e; asm("lg2.approx.f32 %0, %1;" : "=f"(e) : "f"(x)); return e;
}

// ---------------------------------------------------------------------------
// Kernel 1: interleave + fp32 normalize + per-row int8 quantize.
// Also zeroes g_rowsum, g_tdot, g_ticket, and the output scalar.
// ---------------------------------------------------------------------------
__global__ void __launch_bounds__(256) normalize_kernel(
    const float* __restrict__ zis, const float* __restrict__ zjs,
    float* __restrict__ out) {
    int gtid = blockIdx.x * 256 + threadIdx.x;
    if (gtid < NROWS) { g_rowsum[gtid] = 0.f; g_tdot[gtid] = 0.f; }
    if (gtid == 0) { out[0] = 0.f; g_ticket = 0u; }

    int w = threadIdx.x >> 5, lid = threadIdx.x & 31;
    int row = blockIdx.x * 8 + w;
    const float* src = (row & 1) ? (zis + (size_t)(row >> 1) * DIM)
                                 : (zjs + (size_t)(row >> 1) * DIM);
    float4 v0 = *reinterpret_cast<const float4*>(src + lid * 4);
    float4 v1 = *reinterpret_cast<const float4*>(src + 128 + lid * 4);
    float s = v0.x*v0.x + v0.y*v0.y + v0.z*v0.z + v0.w*v0.w
            + v1.x*v1.x + v1.y*v1.y + v1.z*v1.z + v1.w*v1.w;
    float mx = fmaxf(fmaxf(fmaxf(fabsf(v0.x), fabsf(v0.y)),
                           fmaxf(fabsf(v0.z), fabsf(v0.w))),
                     fmaxf(fmaxf(fabsf(v1.x), fabsf(v1.y)),
                           fmaxf(fabsf(v1.z), fabsf(v1.w))));
    #pragma unroll
    for (int o = 16; o > 0; o >>= 1) {
        s  += __shfl_xor_sync(0xFFFFFFFF, s, o);
        mx  = fmaxf(mx, __shfl_xor_sync(0xFFFFFFFF, mx, o));
    }
    float inv = 1.0f / fmaxf(sqrtf(s), 1e-8f);
    float mxn = fmaxf(mx * inv, 1e-20f);
    if (lid == 0) g_sc[row] = mxn * (1.0f / 127.0f);

    float k = inv * (127.0f / mxn);
    int q0 = __float2int_rn(v0.x * k), q1 = __float2int_rn(v0.y * k);
    int q2 = __float2int_rn(v0.z * k), q3 = __float2int_rn(v0.w * k);
    int q4 = __float2int_rn(v1.x * k), q5 = __float2int_rn(v1.y * k);
    int q6 = __float2int_rn(v1.z * k), q7 = __float2int_rn(v1.w * k);
    uint32_t w0 = (q0 & 0xff) | ((q1 & 0xff) << 8)
                | ((q2 & 0xff) << 16) | ((q3 & 0xff) << 24);
    uint32_t w1 = (q4 & 0xff) | ((q5 & 0xff) << 8)
                | ((q6 & 0xff) << 16) | ((q7 & 0xff) << 24);
    uint32_t* dst = reinterpret_cast<uint32_t*>(g_q + (size_t)row * DIM);
    dst[lid]      = w0;
    dst[32 + lid] = w1;
}

// ---------------------------------------------------------------------------
// Kernel 2: persistent IMMA GEMM over the 2080-tile upper triangle.
// 296 CTAs; tiles claimed via global ticket (1-tile lookahead). Pipeline
// unit = one K-half (A 16KB + B 16KB) in a 3-stage smem ring.
// 8 warps (2m x 4n), warp tile 64x32.
// ---------------------------------------------------------------------------
__global__ void __launch_bounds__(256, 2) gemm_kernel() {
    extern __shared__ __align__(16) char smem[];
    __shared__ int s_tq[3];                   // tile-id queue, slot = k % 3
    const uint32_t sb = smem_u32(smem);
    const int tid = threadIdx.x;
    const int lid = tid & 31;
    const int wid = tid >> 5;
    const int wm = wid >> 2;
    const int wn = wid & 3;
    const int wrow = wm * 64;
    const int wcol = wn * 32;

    auto decode = [&](int t, int& by, int& bx) {
        int yy = t / 65, xx = t - yy * 65;
        if (xx < 64 - yy) { by = yy;      bx = yy + xx; }
        else              { by = 63 - yy; bx = xx - 1;  }
    };

    // issue one K-half of tile t into stage s (guarded); ALWAYS commits.
    auto issue_half = [&](int t, int k, int s) {
        if (t < NT_TOT) {
            int by, bx;
            decode(t, by, bx);
            bool diag = (bx == by);
            uint32_t dA = sb + (uint32_t)s * 32768u;
            const char* srcA = (const char*)g_q + (size_t)by * 32768 + k * 128;
            #pragma unroll
            for (int it = 0; it < 4; it++) {
                int i = it * 256 + tid;
                int r = i >> 3, g = i & 7;
                uint32_t off = (uint32_t)(r * 128 + ((g * 16) ^ ((r & 7) << 4)));
                cp16(dA + off, srcA + (size_t)r * 256 + g * 16);
            }
            if (!diag) {
                uint32_t dB = dA + 16384u;
                const char* srcB = (const char*)g_q + (size_t)bx * 32768 + k * 128;
                #pragma unroll
                for (int it = 0; it < 4; it++) {
                    int i = it * 256 + tid;
                    int r = i >> 3, g = i & 7;
                    uint32_t off = (uint32_t)(r * 128 + ((g * 16) ^ ((r & 7) << 4)));
                    cp16(dB + off, srcB + (size_t)r * 256 + g * 16);
                }
            }
        }
        asm volatile("cp.async.commit_group;" ::: "memory");
    };

    const int lg = lid & 7;
    const int ltile = lid >> 3;
    const int trow8 = (ltile & 1) * 8;
    const int tk16 = (ltile >> 1) * 16;

    int c[4][4][4];
    #pragma unroll
    for (int mi = 0; mi < 4; mi++)
        #pragma unroll
        for (int ni = 0; ni < 4; ni++)
            #pragma unroll
            for (int q = 0; q < 4; q++) c[mi][ni][q] = 0;

    auto compute = [&](int s, bool diag) {
        uint32_t asb = sb + (uint32_t)s * 32768u;
        uint32_t bsb = diag ? asb : (asb + 16384u);
        #pragma unroll
        for (int k32 = 0; k32 < 4; k32++) {
            int kb = k32 * 32 + tk16;
            uint32_t a[4][4], bb[2][4];
            #pragma unroll
            for (int mi = 0; mi < 4; mi++) {
                int m = wrow + mi * 16 + trow8 + lg;
                ldsm_x4(a[mi], asb + (uint32_t)(m * 128 + (kb ^ ((m & 7) << 4))));
            }
            #pragma unroll
            for (int nb = 0; nb < 2; nb++) {
                int n = wcol + nb * 16 + trow8 + lg;
                ldsm_x4(bb[nb], bsb + (uint32_t)(n * 128 + (kb ^ ((n & 7) << 4))));
            }
            #pragma unroll
            for (int mi = 0; mi < 4; mi++) {
                #pragma unroll
                for (int ni = 0; ni < 4; ni++) {
                    const uint32_t* B = bb[ni >> 1];
                    uint32_t b0 = (ni & 1) ? B[1] : B[0];
                    uint32_t b1 = (ni & 1) ? B[3] : B[2];
                    imma16832(c[mi][ni], a[mi], b0, b1);
                }
            }
        }
    };

    const float C1 = 2.885390081777927f;        // 2*log2(e)
    const float IC1 = 0.34657359027997264f;     // ln2/2

    auto epilogue = [&](int by, int bx, bool diag) {
        const int row0 = by * 128, col0 = bx * 128;
        float s0c[4], s1c[4];
        #pragma unroll
        for (int mi = 0; mi < 4; mi++) {
            int rl0 = wrow + mi * 16 + (lid >> 2);
            s0c[mi] = g_sc[row0 + rl0] * C1;
            s1c[mi] = g_sc[row0 + rl0 + 8] * C1;
        }
        float2 cscr[4];
        #pragma unroll
        for (int ni = 0; ni < 4; ni++)
            cscr[ni] = ((const float2*)g_sc)[bx * 64 + wn * 16 + ni * 4 + (lid & 3)];

        float rs[4][2], cs[4][2];
        #pragma unroll
        for (int i = 0; i < 4; i++) { rs[i][0]=rs[i][1]=0.f; cs[i][0]=cs[i][1]=0.f; }

        #pragma unroll
        for (int mi = 0; mi < 4; mi++) {
            int r0 = row0 + wrow + mi * 16 + (lid >> 2);
            int r1 = r0 + 8;
            #pragma unroll
            for (int ni = 0; ni < 4; ni++) {
                int cb = col0 + wcol + ni * 8 + (lid & 3) * 2;
                float sc0 = cscr[ni].x, sc1 = cscr[ni].y;
                float d0 = (float)c[mi][ni][0] * (s0c[mi] * sc0);
                float d1 = (float)c[mi][ni][1] * (s0c[mi] * sc1);
                float d2 = (float)c[mi][ni][2] * (s1c[mi] * sc0);
                float d3 = (float)c[mi][ni][3] * (s1c[mi] * sc1);
                float e0 = fexp2(d0 - C1);
                float e1 = fexp2(d1 - C1);
                float e2 = fexp2(d2 - C1);
                float e3 = fexp2(d3 - C1);
                if (diag) {
                    if (cb     == r0) e0 = 0.f;
                    if (cb + 1 == r0) e1 = 0.f;
                    if (cb     == r1) e2 = 0.f;
                    if (cb + 1 == r1) e3 = 0.f;
                    if (cb     == (r0 ^ 1)) g_tdot[r0] = d0 * IC1;
                    if (cb + 1 == (r0 ^ 1)) g_tdot[r0] = d1 * IC1;
                    if (cb     == (r1 ^ 1)) g_tdot[r1] = d2 * IC1;
                    if (cb + 1 == (r1 ^ 1)) g_tdot[r1] = d3 * IC1;
                }
                rs[mi][0] += e0 + e1;
                rs[mi][1] += e2 + e3;
                cs[ni][0] += e0 + e2;
                cs[ni][1] += e1 + e3;
            }
        }
        #pragma unroll
        for (int mi = 0; mi < 4; mi++) {
            #pragma unroll
            for (int h = 0; h < 2; h++) {
                float v = rs[mi][h];
                v += __shfl_xor_sync(0xFFFFFFFF, v, 1);
                v += __shfl_xor_sync(0xFFFFFFFF, v, 2);
                if ((lid & 3) == 0)
                    atomicAdd(&g_rowsum[row0 + wrow + mi*16 + (lid >> 2) + h*8], v);
            }
        }
        if (!diag) {
            #pragma unroll
            for (int ni = 0; ni < 4; ni++) {
                #pragma unroll
                for (int h = 0; h < 2; h++) {
                    float v = cs[ni][h];
                    v += __shfl_xor_sync(0xFFFFFFFF, v, 4);
                    v += __shfl_xor_sync(0xFFFFFFFF, v, 8);
                    v += __shfl_xor_sync(0xFFFFFFFF, v, 16);
                    if (lid < 4)
                        atomicAdd(&g_rowsum[col0 + wcol + ni*8 + lid*2 + h], v);
                }
            }
        }
        #pragma unroll
        for (int mi = 0; mi < 4; mi++)
            #pragma unroll
            for (int ni = 0; ni < 4; ni++)
                #pragma unroll
                for (int q = 0; q < 4; q++) c[mi][ni][q] = 0;
    };

    // ---- prologue: acquire tiles 0 and 1 (queue slots 0 and 1) ----
    if (tid == 0) {
        s_tq[0] = (int)atomicAdd(&g_ticket, 1u);
        s_tq[1] = (int)atomicAdd(&g_ticket, 1u);
    }
    __syncthreads();
    issue_half(s_tq[0], 0, 0);     // half 0 -> stage 0 (commit G0)
    issue_half(s_tq[0], 1, 1);     // half 1 -> stage 1 (commit G1)

    // ---- main pipeline over halves h; local tile ordinal k = h/2 ----
    for (int h = 0; ; h++) {
        const int k = h >> 1;
        asm volatile("cp.async.wait_group 1;" ::: "memory");
        __syncthreads();           // half h visible; slot writes 2 iters old

        const int tcur = s_tq[k % 3];
        if (tcur >= NT_TOT) break;

        // even h: acquire tile k+2 into slot (k+2)%3 (used from iter h+2)
        if ((h & 1) == 0 && tid == 0)
            s_tq[(k + 2) % 3] = (int)atomicAdd(&g_ticket, 1u);

        // issue half h+2 (tile k+1, acquired >= 2 iterations ago)
        issue_half(s_tq[((h + 2) >> 1) % 3], (h + 2) & 1, (h + 2) % 3);

        int by, bx;
        decode(tcur, by, bx);
        const bool dg = (bx == by);
        compute(h % 3, dg);
        if (h & 1) epilogue(by, bx, dg);
    }
    asm volatile("cp.async.wait_group 0;" ::: "memory");   // drain
}

// ---------------------------------------------------------------------------
// Kernel 3: final reduction -> mean loss (32 blocks, atomic combine).
// ---------------------------------------------------------------------------
__global__ void __launch_bounds__(256) finalize_kernel(float* __restrict__ out) {
    int r = blockIdx.x * 256 + threadIdx.x;
    const float LN2 = 0.6931471805599453f;
    float acc = 2.f + LN2 * flg2(g_rowsum[r]) - 2.f * g_tdot[r];
    #pragma unroll
    for (int o = 16; o > 0; o >>= 1) acc += __shfl_xor_sync(0xFFFFFFFF, acc, o);
    __shared__ float sh[8];
    int w = threadIdx.x >> 5, l = threadIdx.x & 31;
    if (l == 0) sh[w] = acc;
    __syncthreads();
    if (threadIdx.x < 8) {
        float v = sh[threadIdx.x];
        v += __shfl_xor_sync(0xFF, v, 1);
        v += __shfl_xor_sync(0xFF, v, 2);
        v += __shfl_xor_sync(0xFF, v, 4);
        if (threadIdx.x == 0) atomicAdd(out, v * (1.0f / (float)NROWS));
    }
}

// ---------------------------------------------------------------------------
extern "C" void kernel_launch(void* const* d_in, const int* in_sizes, int n_in,
                              void* d_out, int out_size) {
    const float* zis = (const float*)d_in[0];
    const float* zjs = (const float*)d_in[1];
    float* out = (float*)d_out;

    cudaFuncSetAttribute(gemm_kernel,
                         cudaFuncAttributeMaxDynamicSharedMemorySize, SMEM_TOTAL);

    normalize_kernel<<<NROWS / 8, 256>>>(zis, zjs, out);
    gemm_kernel<<<296, 256, SMEM_TOTAL>>>();
    finalize_kernel<<<NROWS / 256, 256>>>(out);
}

// round 15
// speedup vs baseline: 1.1635x; 1.1635x over previous
#include <cuda_runtime.h>
#include <math.h>
#include <stdint.h>

// NT-Xent loss. N=8192 rows (interleaved zjs/zis), D=256.
// score = 2*cos(i,j) in [-2,2] -> fixed-shift logsumexp:
//   loss_i = 2 + ln(sum_{j!=i} exp(2 d_ij - 2)) - 2 d_{i, i^1}
// Symmetric int8 IMMA GEMM, exact triangular grid (2080 CTAs, 256 thr,
// 8 warps 64x32, 2 CTAs/SM). K split into 4 quarters in a 4-stage
// cp.async ring -> first MMA starts after 16KB, not 32KB.

#define NROWS 8192
#define DIM   256

__device__ __align__(16) int8_t g_q[NROWS * DIM];   // 2 MB quantized rows
__device__ __align__(16) float g_sc[NROWS];         // per-row dequant scale
__device__ float g_rowsum[NROWS];
__device__ float g_tdot[NROWS];

// ---------------- helpers ----------------
__device__ __forceinline__ uint32_t smem_u32(const void* p) {
    uint32_t a;
    asm("{ .reg .u64 t; cvta.to.shared.u64 t, %1; cvt.u32.u64 %0, t; }"
        : "=r"(a) : "l"(p));
    return a;
}
__device__ __forceinline__ void cp16(uint32_t dst, const void* src) {
    asm volatile("cp.async.cg.shared.global [%0], [%1], 16;"
                 :: "r"(dst), "l"(src) : "memory");
}
__device__ __forceinline__ void ldsm_x4(uint32_t* r, uint32_t addr) {
    asm volatile("ldmatrix.sync.aligned.m8n8.x4.shared.b16 {%0,%1,%2,%3}, [%4];"
                 : "=r"(r[0]), "=r"(r[1]), "=r"(r[2]), "=r"(r[3]) : "r"(addr));
}
__device__ __forceinline__ void imma16832(int* c, const uint32_t* a,
                                          uint32_t b0, uint32_t b1) {
    asm volatile("mma.sync.aligned.m16n8k32.row.col.s32.s8.s8.s32 "
                 "{%0,%1,%2,%3}, {%4,%5,%6,%7}, {%8,%9}, {%0,%1,%2,%3};"
                 : "+r"(c[0]), "+r"(c[1]), "+r"(c[2]), "+r"(c[3])
                 : "r"(a[0]), "r"(a[1]), "r"(a[2]), "r"(a[3]), "r"(b0), "r"(b1));
}
__device__ __forceinline__ float fexp2(float x) {
    float e; asm("ex2.approx.ftz.f32 %0, %1;" : "=f"(e) : "f"(x)); return e;
}
__device__ __forceinline__ float flg2(float x) {
    float e; asm("lg2.approx.f32 %0, %1;" : "=f"(e) : "f"(x)); return e;
}

// ---------------------------------------------------------------------------
// Kernel 1: interleave + fp32 normalize + per-row int8 quantize.
// 2 rows per warp (doubled MLP). grid = 512 x 256. Zeroes scratch + out.
// ---------------------------------------------------------------------------
__global__ void __launch_bounds__(256) normalize_kernel(
    const float* __restrict__ zis, const float* __restrict__ zjs,
    float* __restrict__ out) {
    int gtid = blockIdx.x * 256 + threadIdx.x;
    if (gtid < NROWS) { g_rowsum[gtid] = 0.f; g_tdot[gtid] = 0.f; }
    if (gtid == 0) out[0] = 0.f;

    int w = threadIdx.x >> 5, lid = threadIdx.x & 31;
    int pair = blockIdx.x * 8 + w;          // rows 2*pair (zjs), 2*pair+1 (zis)
    const float* sa = zjs + (size_t)pair * DIM;
    const float* sb = zis + (size_t)pair * DIM;
    float4 a0 = *reinterpret_cast<const float4*>(sa + lid * 4);
    float4 a1 = *reinterpret_cast<const float4*>(sa + 128 + lid * 4);
    float4 b0 = *reinterpret_cast<const float4*>(sb + lid * 4);
    float4 b1 = *reinterpret_cast<const float4*>(sb + 128 + lid * 4);

    float sA = a0.x*a0.x + a0.y*a0.y + a0.z*a0.z + a0.w*a0.w
             + a1.x*a1.x + a1.y*a1.y + a1.z*a1.z + a1.w*a1.w;
    float sB = b0.x*b0.x + b0.y*b0.y + b0.z*b0.z + b0.w*b0.w
             + b1.x*b1.x + b1.y*b1.y + b1.z*b1.z + b1.w*b1.w;
    float mA = fmaxf(fmaxf(fmaxf(fabsf(a0.x), fabsf(a0.y)),
                           fmaxf(fabsf(a0.z), fabsf(a0.w))),
                     fmaxf(fmaxf(fabsf(a1.x), fabsf(a1.y)),
                           fmaxf(fabsf(a1.z), fabsf(a1.w))));
    float mB = fmaxf(fmaxf(fmaxf(fabsf(b0.x), fabsf(b0.y)),
                           fmaxf(fabsf(b0.z), fabsf(b0.w))),
                     fmaxf(fmaxf(fabsf(b1.x), fabsf(b1.y)),
                           fmaxf(fabsf(b1.z), fabsf(b1.w))));
    #pragma unroll
    for (int o = 16; o > 0; o >>= 1) {
        sA += __shfl_xor_sync(0xFFFFFFFF, sA, o);
        sB += __shfl_xor_sync(0xFFFFFFFF, sB, o);
        mA  = fmaxf(mA, __shfl_xor_sync(0xFFFFFFFF, mA, o));
        mB  = fmaxf(mB, __shfl_xor_sync(0xFFFFFFFF, mB, o));
    }
    float invA = 1.0f / fmaxf(sqrtf(sA), 1e-8f);
    float invB = 1.0f / fmaxf(sqrtf(sB), 1e-8f);
    float mxA = fmaxf(mA * invA, 1e-20f);
    float mxB = fmaxf(mB * invB, 1e-20f);
    if (lid == 0) {
        g_sc[2 * pair]     = mxA * (1.0f / 127.0f);
        g_sc[2 * pair + 1] = mxB * (1.0f / 127.0f);
    }

    float kA = invA * (127.0f / mxA);
    float kB = invB * (127.0f / mxB);
    #pragma unroll
    for (int half = 0; half < 2; half++) {
        float4 va = half ? a1 : a0;
        float4 vb = half ? b1 : b0;
        int qa0 = __float2int_rn(va.x * kA), qa1 = __float2int_rn(va.y * kA);
        int qa2 = __float2int_rn(va.z * kA), qa3 = __float2int_rn(va.w * kA);
        int qb0 = __float2int_rn(vb.x * kB), qb1 = __float2int_rn(vb.y * kB);
        int qb2 = __float2int_rn(vb.z * kB), qb3 = __float2int_rn(vb.w * kB);
        uint32_t wa = (qa0 & 0xff) | ((qa1 & 0xff) << 8)
                    | ((qa2 & 0xff) << 16) | ((qa3 & 0xff) << 24);
        uint32_t wb = (qb0 & 0xff) | ((qb1 & 0xff) << 8)
                    | ((qb2 & 0xff) << 16) | ((qb3 & 0xff) << 24);
        uint32_t* dA = reinterpret_cast<uint32_t*>(g_q + (size_t)(2*pair) * DIM);
        uint32_t* dB = reinterpret_cast<uint32_t*>(g_q + (size_t)(2*pair+1) * DIM);
        dA[half * 32 + lid] = wa;
        dB[half * 32 + lid] = wb;
    }
}

// ---------------------------------------------------------------------------
// Kernel 2: upper-triangle 128x128 int8 IMMA tiles + symmetric epilogue.
// grid (65, 32) packs the 2080-tile triangle exactly.
// 8 warps (2m x 4n), warp tile 64x32. 4-stage K-quarter ring (4x16KB)
// + scales (1 KB). 64B rows, swizzle (g*16) ^ (((r>>1)&3)<<4).
// ---------------------------------------------------------------------------
#define SM_SCALES 65536u
#define SMEM_TOTAL 66560

__global__ void __launch_bounds__(256, 2) gemm_kernel() {
    // triangular decode: pair row y (len 64-y) with row 63-y (len y+1)
    const int x = blockIdx.x, y = blockIdx.y;
    int by, bx;
    if (x < 64 - y) { by = y;      bx = y + x; }
    else            { by = 63 - y; bx = x - 1; }
    const bool diag = (bx == by);

    extern __shared__ __align__(16) char smem[];
    const uint32_t sb = smem_u32(smem);
    const int tid = threadIdx.x;
    const int lid = tid & 31;
    const int wid = tid >> 5;
    const int wm = wid >> 2;
    const int wn = wid & 3;
    const int wrow = wm * 64;
    const int wcol = wn * 32;
    const int row0 = by * 128;
    const int col0 = bx * 128;

    int c[4][4][4];
    #pragma unroll
    for (int mi = 0; mi < 4; mi++)
        #pragma unroll
        for (int ni = 0; ni < 4; ni++)
            #pragma unroll
            for (int q = 0; q < 4; q++) c[mi][ni][q] = 0;

    const char* gA = (const char*)g_q + (size_t)row0 * 256;
    const char* gB = (const char*)g_q + (size_t)col0 * 256;

    // scales into smem (row[128] then col[128] floats)
    if (tid < 128) {
        ((float*)(smem + SM_SCALES))[tid]       = g_sc[row0 + tid];
        ((float*)(smem + SM_SCALES))[128 + tid] = g_sc[col0 + tid];
    }

    // ---- quarter loader: 64B of each row of A (+B if offdiag) -> stage s ----
    auto load_q = [&](int q, int s) {
        uint32_t dA = sb + (uint32_t)s * 16384u;
        const char* srcA = gA + q * 64;
        #pragma unroll
        for (int it = 0; it < 2; it++) {
            int i = it * 256 + tid;          // 0..511
            int r = i >> 2, g = i & 3;
            uint32_t off = (uint32_t)(r * 64 + ((g * 16) ^ (((r >> 1) & 3) << 4)));
            cp16(dA + off, srcA + (size_t)r * 256 + g * 16);
        }
        if (!diag) {
            uint32_t dB = dA + 8192u;
            const char* srcB = gB + q * 64;
            #pragma unroll
            for (int it = 0; it < 2; it++) {
                int i = it * 256 + tid;
                int r = i >> 2, g = i & 3;
                uint32_t off = (uint32_t)(r * 64 + ((g * 16) ^ (((r >> 1) & 3) << 4)));
                cp16(dB + off, srcB + (size_t)r * 256 + g * 16);
            }
        }
        asm volatile("cp.async.commit_group;" ::: "memory");
    };

    const int lg = lid & 7;
    const int ltile = lid >> 3;
    const int trow8 = (ltile & 1) * 8;
    const int tk16 = (ltile >> 1) * 16;

    auto compute = [&](int s) {
        uint32_t asb = sb + (uint32_t)s * 16384u;
        uint32_t bsb = diag ? asb : (asb + 8192u);
        #pragma unroll
        for (int k32 = 0; k32 < 2; k32++) {
            int kb = k32 * 32 + tk16;
            uint32_t a[4][4], bb[2][4];
            #pragma unroll
            for (int mi = 0; mi < 4; mi++) {
                int m = wrow + mi * 16 + trow8 + lg;
                ldsm_x4(a[mi], asb + (uint32_t)(m * 64 + (kb ^ (((m >> 1) & 3) << 4))));
            }
            #pragma unroll
            for (int nb = 0; nb < 2; nb++) {
                int n = wcol + nb * 16 + trow8 + lg;
                ldsm_x4(bb[nb], bsb + (uint32_t)(n * 64 + (kb ^ (((n >> 1) & 3) << 4))));
            }
            #pragma unroll
            for (int mi = 0; mi < 4; mi++) {
                #pragma unroll
                for (int ni = 0; ni < 4; ni++) {
                    const uint32_t* B = bb[ni >> 1];
                    uint32_t b0 = (ni & 1) ? B[1] : B[0];
                    uint32_t b1 = (ni & 1) ? B[3] : B[2];
                    imma16832(c[mi][ni], a[mi], b0, b1);
                }
            }
        }
    };

    // ---- 4 quarters, all issued upfront; compute as each lands ----
    load_q(0, 0);
    load_q(1, 1);
    load_q(2, 2);
    load_q(3, 3);
    asm volatile("cp.async.wait_group 3;" ::: "memory");
    __syncthreads();
    compute(0);
    asm volatile("cp.async.wait_group 2;" ::: "memory");
    __syncthreads();
    compute(1);
    asm volatile("cp.async.wait_group 1;" ::: "memory");
    __syncthreads();
    compute(2);
    asm volatile("cp.async.wait_group 0;" ::: "memory");
    __syncthreads();
    compute(3);

    // ---- epilogue: dequant + shifted exp-sum; reductions -> global RED ----
    const float C1 = 2.885390081777927f;   // 2*log2(e)
    const float IC1 = 0.34657359027997264f;  // ln2/2
    const float* rsc = (const float*)(smem + SM_SCALES);
    const float* csc = rsc + 128;

    float rs[4][2], cs[4][2];
    #pragma unroll
    for (int i = 0; i < 4; i++) { rs[i][0]=rs[i][1]=0.f; cs[i][0]=cs[i][1]=0.f; }

    #pragma unroll
    for (int mi = 0; mi < 4; mi++) {
        int rl0 = wrow + mi * 16 + (lid >> 2);
        int rl1 = rl0 + 8;
        int r0 = row0 + rl0, r1 = row0 + rl1;
        float s0 = rsc[rl0] * C1, s1 = rsc[rl1] * C1;
        #pragma unroll
        for (int ni = 0; ni < 4; ni++) {
            int cl = wcol + ni * 8 + (lid & 3) * 2;
            int cb = col0 + cl;
            float sc0 = csc[cl], sc1 = csc[cl + 1];
            float d0 = (float)c[mi][ni][0] * (s0 * sc0);
            float d1 = (float)c[mi][ni][1] * (s0 * sc1);
            float d2 = (float)c[mi][ni][2] * (s1 * sc0);
            float d3 = (float)c[mi][ni][3] * (s1 * sc1);
            float e0 = fexp2(d0 - C1);
            float e1 = fexp2(d1 - C1);
            float e2 = fexp2(d2 - C1);
            float e3 = fexp2(d3 - C1);
            if (diag) {
                if (cb     == r0) e0 = 0.f;
                if (cb + 1 == r0) e1 = 0.f;
                if (cb     == r1) e2 = 0.f;
                if (cb + 1 == r1) e3 = 0.f;
                if (cb     == (r0 ^ 1)) g_tdot[r0] = d0 * IC1;
                if (cb + 1 == (r0 ^ 1)) g_tdot[r0] = d1 * IC1;
                if (cb     == (r1 ^ 1)) g_tdot[r1] = d2 * IC1;
                if (cb + 1 == (r1 ^ 1)) g_tdot[r1] = d3 * IC1;
            }
            rs[mi][0] += e0 + e1;
            rs[mi][1] += e2 + e3;
            cs[ni][0] += e0 + e2;
            cs[ni][1] += e1 + e3;
        }
    }

    // rows: shfl-reduce across the 4 lanes sharing each row -> global RED
    #pragma unroll
    for (int mi = 0; mi < 4; mi++) {
        #pragma unroll
        for (int h = 0; h < 2; h++) {
            float v = rs[mi][h];
            v += __shfl_xor_sync(0xFFFFFFFF, v, 1);
            v += __shfl_xor_sync(0xFFFFFFFF, v, 2);
            if ((lid & 3) == 0)
                atomicAdd(&g_rowsum[row0 + wrow + mi * 16 + (lid >> 2) + h * 8], v);
        }
    }
    // cols (offdiag only): shfl-reduce across 8 lanes -> global RED
    if (!diag) {
        #pragma unroll
        for (int ni = 0; ni < 4; ni++) {
            #pragma unroll
            for (int h = 0; h < 2; h++) {
                float v = cs[ni][h];
                v += __shfl_xor_sync(0xFFFFFFFF, v, 4);
                v += __shfl_xor_sync(0xFFFFFFFF, v, 8);
                v += __shfl_xor_sync(0xFFFFFFFF, v, 16);
                if (lid < 4)
                    atomicAdd(&g_rowsum[col0 + wcol + ni * 8 + lid * 2 + h], v);
            }
        }
    }
}

// ---------------------------------------------------------------------------
// Kernel 3: final reduction -> mean loss (32 blocks, atomic combine).
// ---------------------------------------------------------------------------
__global__ void __launch_bounds__(256) finalize_kernel(float* __restrict__ out) {
    int r = blockIdx.x * 256 + threadIdx.x;
    const float LN2 = 0.6931471805599453f;
    float acc = 2.f + LN2 * flg2(g_rowsum[r]) - 2.f * g_tdot[r];
    #pragma unroll
    for (int o = 16; o > 0; o >>= 1) acc += __shfl_xor_sync(0xFFFFFFFF, acc, o);
    __shared__ float sh[8];
    int w = threadIdx.x >> 5, l = threadIdx.x & 31;
    if (l == 0) sh[w] = acc;
    __syncthreads();
    if (threadIdx.x < 8) {
        float v = sh[threadIdx.x];
        v += __shfl_xor_sync(0xFF, v, 1);
        v += __shfl_xor_sync(0xFF, v, 2);
        v += __shfl_xor_sync(0xFF, v, 4);
        if (threadIdx.x == 0) atomicAdd(out, v * (1.0f / (float)NROWS));
    }
}

// ---------------------------------------------------------------------------
extern "C" void kernel_launch(void* const* d_in, const int* in_sizes, int n_in,
                              void* d_out, int out_size) {
    const float* zis = (const float*)d_in[0];
    const float* zjs = (const float*)d_in[1];
    float* out = (float*)d_out;

    cudaFuncSetAttribute(gemm_kernel,
                         cudaFuncAttributeMaxDynamicSharedMemorySize, SMEM_TOTAL);

    normalize_kernel<<<NROWS / 16, 256>>>(zis, zjs, out);
    dim3 grid(65, 32);
    gemm_kernel<<<grid, 256, SMEM_TOTAL>>>();
    finalize_kernel<<<NROWS / 256, 256>>>(out);
}

// round 16
// speedup vs baseline: 1.2131x; 1.0426x over previous
#include <cuda_runtime.h>
#include <math.h>
#include <stdint.h>

// NT-Xent loss. N=8192 rows (interleaved zjs/zis), D=256.
// score = 2*cos(i,j) in [-2,2] -> fixed-shift logsumexp:
//   loss_i = 2 + ln(sum_{j!=i} exp(2 d_ij - 2)) - 2 d_{i, i^1}
// Symmetric int8 IMMA GEMM, 2080 CTAs (8 warps 64x32, 2 CTAs/SM, 2-stage
// cp.async). Tile order: 2016 off-diag first (balanced row pairs), the 64
// cheap DIAGONAL tiles launched LAST so the fractional 8-CTA tail wave is
// half-cost work.

#define NROWS 8192
#define DIM   256

__device__ __align__(16) int8_t g_q[NROWS * DIM];   // 2 MB quantized rows
__device__ __align__(16) float g_sc[NROWS];         // per-row dequant scale
__device__ float g_rowsum[NROWS];
__device__ float g_tdot[NROWS];

// ---------------- helpers ----------------
__device__ __forceinline__ uint32_t smem_u32(const void* p) {
    uint32_t a;
    asm("{ .reg .u64 t; cvta.to.shared.u64 t, %1; cvt.u32.u64 %0, t; }"
        : "=r"(a) : "l"(p));
    return a;
}
__device__ __forceinline__ void cp16(uint32_t dst, const void* src) {
    asm volatile("cp.async.cg.shared.global [%0], [%1], 16;"
                 :: "r"(dst), "l"(src) : "memory");
}
__device__ __forceinline__ void ldsm_x4(uint32_t* r, uint32_t addr) {
    asm volatile("ldmatrix.sync.aligned.m8n8.x4.shared.b16 {%0,%1,%2,%3}, [%4];"
                 : "=r"(r[0]), "=r"(r[1]), "=r"(r[2]), "=r"(r[3]) : "r"(addr));
}
__device__ __forceinline__ void imma16832(int* c, const uint32_t* a,
                                          uint32_t b0, uint32_t b1) {
    asm volatile("mma.sync.aligned.m16n8k32.row.col.s32.s8.s8.s32 "
                 "{%0,%1,%2,%3}, {%4,%5,%6,%7}, {%8,%9}, {%0,%1,%2,%3};"
                 : "+r"(c[0]), "+r"(c[1]), "+r"(c[2]), "+r"(c[3])
                 : "r"(a[0]), "r"(a[1]), "r"(a[2]), "r"(a[3]), "r"(b0), "r"(b1));
}
__device__ __forceinline__ float fexp2(float x) {
    float e; asm("ex2.approx.ftz.f32 %0, %1;" : "=f"(e) : "f"(x)); return e;
}
__device__ __forceinline__ float flg2(float x) {
    float e; asm("lg2.approx.f32 %0, %1;" : "=f"(e) : "f"(x)); return e;
}

// ---------------------------------------------------------------------------
// Kernel 1: interleave + fp32 normalize + per-row int8 quantize.
// One warp per row (proven best). Zeroes g_rowsum, g_tdot, out.
// ---------------------------------------------------------------------------
__global__ void __launch_bounds__(256) normalize_kernel(
    const float* __restrict__ zis, const float* __restrict__ zjs,
    float* __restrict__ out) {
    int gtid = blockIdx.x * 256 + threadIdx.x;
    if (gtid < NROWS) { g_rowsum[gtid] = 0.f; g_tdot[gtid] = 0.f; }
    if (gtid == 0) out[0] = 0.f;

    int w = threadIdx.x >> 5, lid = threadIdx.x & 31;
    int row = blockIdx.x * 8 + w;
    const float* src = (row & 1) ? (zis + (size_t)(row >> 1) * DIM)
                                 : (zjs + (size_t)(row >> 1) * DIM);
    float4 v0 = *reinterpret_cast<const float4*>(src + lid * 4);
    float4 v1 = *reinterpret_cast<const float4*>(src + 128 + lid * 4);
    float s = v0.x*v0.x + v0.y*v0.y + v0.z*v0.z + v0.w*v0.w
            + v1.x*v1.x + v1.y*v1.y + v1.z*v1.z + v1.w*v1.w;
    float mx = fmaxf(fmaxf(fmaxf(fabsf(v0.x), fabsf(v0.y)),
                           fmaxf(fabsf(v0.z), fabsf(v0.w))),
                     fmaxf(fmaxf(fabsf(v1.x), fabsf(v1.y)),
                           fmaxf(fabsf(v1.z), fabsf(v1.w))));
    #pragma unroll
    for (int o = 16; o > 0; o >>= 1) {
        s  += __shfl_xor_sync(0xFFFFFFFF, s, o);
        mx  = fmaxf(mx, __shfl_xor_sync(0xFFFFFFFF, mx, o));
    }
    float inv = 1.0f / fmaxf(sqrtf(s), 1e-8f);
    float mxn = fmaxf(mx * inv, 1e-20f);
    if (lid == 0) g_sc[row] = mxn * (1.0f / 127.0f);

    float k = inv * (127.0f / mxn);
    int q0 = __float2int_rn(v0.x * k), q1 = __float2int_rn(v0.y * k);
    int q2 = __float2int_rn(v0.z * k), q3 = __float2int_rn(v0.w * k);
    int q4 = __float2int_rn(v1.x * k), q5 = __float2int_rn(v1.y * k);
    int q6 = __float2int_rn(v1.z * k), q7 = __float2int_rn(v1.w * k);
    uint32_t w0 = (q0 & 0xff) | ((q1 & 0xff) << 8)
                | ((q2 & 0xff) << 16) | ((q3 & 0xff) << 24);
    uint32_t w1 = (q4 & 0xff) | ((q5 & 0xff) << 8)
                | ((q6 & 0xff) << 16) | ((q7 & 0xff) << 24);
    uint32_t* dst = reinterpret_cast<uint32_t*>(g_q + (size_t)row * DIM);
    dst[lid]      = w0;
    dst[32 + lid] = w1;
}

// ---------------------------------------------------------------------------
// Kernel 2: 128x128 int8 IMMA tiles + symmetric epilogue.
// 1D grid of 2080. bid < 2016: off-diag (pair q with 63-q, 63 tiles/pair);
// bid >= 2016: diagonal tile (launched last -> cheap tail wave).
// 8 warps (2m x 4n), warp tile 64x32. 2-stage smem (64 KB) + scales (1 KB).
// ---------------------------------------------------------------------------
#define SM_SCALES 65536u
#define SMEM_TOTAL 66560

__global__ void __launch_bounds__(256, 2) gemm_kernel() {
    int by, bx;
    {
        const int bid = blockIdx.x;
        if (bid < 2016) {
            int q = bid / 63, r = bid - q * 63;
            if (r < 63 - q) { by = q;      bx = q + 1 + r; }
            else            { by = 63 - q; bx = r + 1;     }
        } else {
            by = bx = bid - 2016;
        }
    }
    const bool diag = (bx == by);

    extern __shared__ __align__(16) char smem[];
    const uint32_t sb = smem_u32(smem);
    const int tid = threadIdx.x;
    const int lid = tid & 31;
    const int wid = tid >> 5;
    const int wm = wid >> 2;
    const int wn = wid & 3;
    const int wrow = wm * 64;
    const int wcol = wn * 32;
    const int row0 = by * 128;
    const int col0 = bx * 128;

    int c[4][4][4];
    #pragma unroll
    for (int mi = 0; mi < 4; mi++)
        #pragma unroll
        for (int ni = 0; ni < 4; ni++)
            #pragma unroll
            for (int q = 0; q < 4; q++) c[mi][ni][q] = 0;

    const char* gA = (const char*)g_q + (size_t)row0 * 256;
    const char* gB = (const char*)g_q + (size_t)col0 * 256;

    // scales into smem (row[128] then col[128] floats)
    if (tid < 128) {
        ((float*)(smem + SM_SCALES))[tid]       = g_sc[row0 + tid];
        ((float*)(smem + SM_SCALES))[128 + tid] = g_sc[col0 + tid];
    }

    // ---- stage loader: K-half ch (128 B of each row) into stage s (32 KB) ----
    auto load_stage = [&](int ch, int s) {
        uint32_t dA = sb + (uint32_t)s * 32768u;
        const char* srcA = gA + ch * 128;
        #pragma unroll
        for (int it = 0; it < 4; it++) {
            int i = it * 256 + tid;          // 0..1023
            int r = i >> 3, g = i & 7;
            uint32_t off = (uint32_t)(r * 128 + ((g * 16) ^ ((r & 7) << 4)));
            cp16(dA + off, srcA + (size_t)r * 256 + g * 16);
        }
        if (!diag) {
            uint32_t dB = dA + 16384u;
            const char* srcB = gB + ch * 128;
            #pragma unroll
            for (int it = 0; it < 4; it++) {
                int i = it * 256 + tid;
                int r = i >> 3, g = i & 7;
                uint32_t off = (uint32_t)(r * 128 + ((g * 16) ^ ((r & 7) << 4)));
                cp16(dB + off, srcB + (size_t)r * 256 + g * 16);
            }
        }
        asm volatile("cp.async.commit_group;" ::: "memory");
    };

    const int lg = lid & 7;
    const int ltile = lid >> 3;
    const int trow8 = (ltile & 1) * 8;
    const int tk16 = (ltile >> 1) * 16;

    auto compute = [&](int s) {
        uint32_t asb = sb + (uint32_t)s * 32768u;
        uint32_t bsb = diag ? asb : (asb + 16384u);
        #pragma unroll
        for (int k32 = 0; k32 < 4; k32++) {
            int kb = k32 * 32 + tk16;
            uint32_t a[4][4], bb[2][4];
            #pragma unroll
            for (int mi = 0; mi < 4; mi++) {
                int m = wrow + mi * 16 + trow8 + lg;
                ldsm_x4(a[mi], asb + (uint32_t)(m * 128 + (kb ^ ((m & 7) << 4))));
            }
            #pragma unroll
            for (int nb = 0; nb < 2; nb++) {
                int n = wcol + nb * 16 + trow8 + lg;
                ldsm_x4(bb[nb], bsb + (uint32_t)(n * 128 + (kb ^ ((n & 7) << 4))));
            }
            #pragma unroll
            for (int mi = 0; mi < 4; mi++) {
                #pragma unroll
                for (int ni = 0; ni < 4; ni++) {
                    const uint32_t* B = bb[ni >> 1];
                    uint32_t b0 = (ni & 1) ? B[1] : B[0];
                    uint32_t b1 = (ni & 1) ? B[3] : B[2];
                    imma16832(c[mi][ni], a[mi], b0, b1);
                }
            }
        }
    };

    // ---- two K-halves, 2-stage pipeline ----
    load_stage(0, 0);
    load_stage(1, 1);
    asm volatile("cp.async.wait_group 1;" ::: "memory");
    __syncthreads();
    compute(0);
    asm volatile("cp.async.wait_group 0;" ::: "memory");
    __syncthreads();
    compute(1);

    // ---- epilogue: dequant + shifted exp-sum; reductions -> global RED ----
    const float C1 = 2.885390081777927f;     // 2*log2(e)
    const float IC1 = 0.34657359027997264f;  // ln2/2
    const float* rsc = (const float*)(smem + SM_SCALES);
    const float* csc = rsc + 128;

    float rs[4][2], cs[4][2];
    #pragma unroll
    for (int i = 0; i < 4; i++) { rs[i][0]=rs[i][1]=0.f; cs[i][0]=cs[i][1]=0.f; }

    #pragma unroll
    for (int mi = 0; mi < 4; mi++) {
        int rl0 = wrow + mi * 16 + (lid >> 2);
        int rl1 = rl0 + 8;
        int r0 = row0 + rl0, r1 = row0 + rl1;
        float s0 = rsc[rl0] * C1, s1 = rsc[rl1] * C1;
        #pragma unroll
        for (int ni = 0; ni < 4; ni++) {
            int cl = wcol + ni * 8 + (lid & 3) * 2;
            int cb = col0 + cl;
            float sc0 = csc[cl], sc1 = csc[cl + 1];
            float d0 = (float)c[mi][ni][0] * (s0 * sc0);
            float d1 = (float)c[mi][ni][1] * (s0 * sc1);
            float d2 = (float)c[mi][ni][2] * (s1 * sc0);
            float d3 = (float)c[mi][ni][3] * (s1 * sc1);
            float e0 = fexp2(d0 - C1);
            float e1 = fexp2(d1 - C1);
            float e2 = fexp2(d2 - C1);
            float e3 = fexp2(d3 - C1);
            if (diag) {
                if (cb     == r0) e0 = 0.f;
                if (cb + 1 == r0) e1 = 0.f;
                if (cb     == r1) e2 = 0.f;
                if (cb + 1 == r1) e3 = 0.f;
                if (cb     == (r0 ^ 1)) g_tdot[r0] = d0 * IC1;
                if (cb + 1 == (r0 ^ 1)) g_tdot[r0] = d1 * IC1;
                if (cb     == (r1 ^ 1)) g_tdot[r1] = d2 * IC1;
                if (cb + 1 == (r1 ^ 1)) g_tdot[r1] = d3 * IC1;
            }
            rs[mi][0] += e0 + e1;
            rs[mi][1] += e2 + e3;
            cs[ni][0] += e0 + e2;
            cs[ni][1] += e1 + e3;
        }
    }

    // rows: shfl-reduce across the 4 lanes sharing each row -> global RED
    #pragma unroll
    for (int mi = 0; mi < 4; mi++) {
        #pragma unroll
        for (int h = 0; h < 2; h++) {
            float v = rs[mi][h];
            v += __shfl_xor_sync(0xFFFFFFFF, v, 1);
            v += __shfl_xor_sync(0xFFFFFFFF, v, 2);
            if ((lid & 3) == 0)
                atomicAdd(&g_rowsum[row0 + wrow + mi * 16 + (lid >> 2) + h * 8], v);
        }
    }
    // cols (offdiag only): shfl-reduce across 8 lanes -> global RED
    if (!diag) {
        #pragma unroll
        for (int ni = 0; ni < 4; ni++) {
            #pragma unroll
            for (int h = 0; h < 2; h++) {
                float v = cs[ni][h];
                v += __shfl_xor_sync(0xFFFFFFFF, v, 4);
                v += __shfl_xor_sync(0xFFFFFFFF, v, 8);
                v += __shfl_xor_sync(0xFFFFFFFF, v, 16);
                if (lid < 4)
                    atomicAdd(&g_rowsum[col0 + wcol + ni * 8 + lid * 2 + h], v);
            }
        }
    }
}

// ---------------------------------------------------------------------------
// Kernel 3: final reduction -> mean loss (32 blocks, atomic combine).
// ---------------------------------------------------------------------------
__global__ void __launch_bounds__(256) finalize_kernel(float* __restrict__ out) {
    int r = blockIdx.x * 256 + threadIdx.x;
    const float LN2 = 0.6931471805599453f;
    float acc = 2.f + LN2 * flg2(g_rowsum[r]) - 2.f * g_tdot[r];
    #pragma unroll
    for (int o = 16; o > 0; o >>= 1) acc += __shfl_xor_sync(0xFFFFFFFF, acc, o);
    __shared__ float sh[8];
    int w = threadIdx.x >> 5, l = threadIdx.x & 31;
    if (l == 0) sh[w] = acc;
    __syncthreads();
    if (threadIdx.x < 8) {
        float v = sh[threadIdx.x];
        v += __shfl_xor_sync(0xFF, v, 1);
        v += __shfl_xor_sync(0xFF, v, 2);
        v += __shfl_xor_sync(0xFF, v, 4);
        if (threadIdx.x == 0) atomicAdd(out, v * (1.0f / (float)NROWS));
    }
}

// ---------------------------------------------------------------------------
extern "C" void kernel_launch(void* const* d_in, const int* in_sizes, int n_in,
                              void* d_out, int out_size) {
    const float* zis = (const float*)d_in[0];
    const float* zjs = (const float*)d_in[1];
    float* out = (float*)d_out;

    cudaFuncSetAttribute(gemm_kernel,
                         cudaFuncAttributeMaxDynamicSharedMemorySize, SMEM_TOTAL);

    normalize_kernel<<<NROWS / 8, 256>>>(zis, zjs, out);
    gemm_kernel<<<2080, 256, SMEM_TOTAL>>>();
    finalize_kernel<<<NROWS / 256, 256>>>(out);
}